// round 1
// baseline (speedup 1.0000x reference)
#include <cuda_runtime.h>
#include <cuda_bf16.h>
#include <cstdint>

#define NN   50000
#define NE   800000
#define NG   64
#define CH   64
#define INCH 128

// ---------------- scratch (static device globals; no allocation) -------------
__device__ float g_dinv[NN];                 // deg -> dinv (in place)
__device__ float g_selfc[NN];                // dinv^2 (self-loop norm)
__device__ float g_norm[NE];                 // per-edge norm
__device__ __align__(16) float g_h[NN * CH];   // h = act @ W
__device__ __align__(16) float g_act[NN * CH]; // layer output (pre-tanh)
__device__ int   g_maxkey[NG * CH];
__device__ float g_sum[NG * CH];
__device__ float g_cnt[NG];

// ---------------- helpers ----------------------------------------------------
__device__ __forceinline__ float acc_tanh(float x) {
    // accurate-enough tanh independent of fast-math flags (~1e-6 rel)
    float e = __expf(-2.0f * fabsf(x));
    float t = (1.0f - e) / (1.0f + e);
    return copysignf(t, x);
}

__device__ __forceinline__ int fkey(float f) {
    int i = __float_as_int(f);
    return (i >= 0) ? i : (i ^ 0x7FFFFFFF);
}
__device__ __forceinline__ float fdec(int k) {
    return __int_as_float((k >= 0) ? k : (k ^ 0x7FFFFFFF));
}

// ---------------- preprocessing ----------------------------------------------
__global__ void k_init_deg() {
    int i = blockIdx.x * blockDim.x + threadIdx.x;
    if (i < NN) g_dinv[i] = 1.0f;   // self-loop weight
}

__global__ void k_accum_deg(const int* __restrict__ ei, const float* __restrict__ w) {
    int e = blockIdx.x * blockDim.x + threadIdx.x;
    if (e < NE) atomicAdd(&g_dinv[ei[NE + e]], w[e]);
}

__global__ void k_dinv() {
    int i = blockIdx.x * blockDim.x + threadIdx.x;
    if (i < NN) {
        float r = rsqrtf(g_dinv[i]);   // deg >= 1 always (self-loop)
        g_dinv[i]  = r;
        g_selfc[i] = r * r;
    }
}

__global__ void k_norm(const int* __restrict__ ei, const float* __restrict__ w) {
    int e = blockIdx.x * blockDim.x + threadIdx.x;
    if (e < NE) g_norm[e] = g_dinv[ei[e]] * w[e] * g_dinv[ei[NE + e]];
}

// ---------------- GEMM: h = act @ W ; out = b + selfc * h ---------------------
// 256 threads, 64 rows/block, K processed in 64-wide chunks.
template <int K, bool FROM_ACT>
__global__ void k_gemm(const float* __restrict__ in,
                       const float* __restrict__ W,
                       const float* __restrict__ b) {
    __shared__ float sA[64 * 65];
    __shared__ float sW[64 * 64];

    const int tid  = threadIdx.x;
    const int row0 = blockIdx.x * 64;
    const int r    = tid >> 2;
    const int cg   = tid & 3;

    const float* A = FROM_ACT ? g_act : in;

    float4 acc[4];
#pragma unroll
    for (int j = 0; j < 4; ++j) acc[j] = make_float4(0.f, 0.f, 0.f, 0.f);

    for (int kc = 0; kc < K; kc += 64) {
        // stage A tile (apply tanh for hidden layers)
#pragma unroll
        for (int idx = tid; idx < 64 * 64; idx += 256) {
            int rr = idx >> 6, kk = idx & 63;
            int grow = row0 + rr;
            float v = 0.0f;
            if (grow < NN) v = A[grow * K + kc + kk];
            if (FROM_ACT) v = acc_tanh(v);
            sA[rr * 65 + kk] = v;
        }
        // stage W chunk (contiguous)
#pragma unroll
        for (int idx = tid; idx < 64 * 64; idx += 256)
            sW[idx] = W[kc * 64 + idx];
        __syncthreads();

#pragma unroll
        for (int k = 0; k < 64; ++k) {
            float a = sA[r * 65 + k];
            const float4* w4 = (const float4*)(sW + k * 64);
#pragma unroll
            for (int j = 0; j < 4; ++j) {
                float4 w = w4[cg * 4 + j];
                acc[j].x += a * w.x;
                acc[j].y += a * w.y;
                acc[j].z += a * w.z;
                acc[j].w += a * w.w;
            }
        }
        __syncthreads();
    }

    int row = row0 + r;
    if (row < NN) {
        float sc = g_selfc[row];
        float4*       h4 = (float4*)(g_h  + row * CH);
        float4*       o4 = (float4*)(g_act + row * CH);
        const float4* b4 = (const float4*)b;
#pragma unroll
        for (int j = 0; j < 4; ++j) {
            int c4 = cg * 4 + j;
            float4 bb = b4[c4];
            h4[c4] = acc[j];
            o4[c4] = make_float4(bb.x + sc * acc[j].x,
                                 bb.y + sc * acc[j].y,
                                 bb.z + sc * acc[j].z,
                                 bb.w + sc * acc[j].w);
        }
    }
}

// ---------------- edge scatter: out[dst] += norm * h[src] ---------------------
// 16 threads per edge, each handles one float4 (4 channels). red.v4 atomics.
__global__ void k_scatter(const int* __restrict__ ei) {
    int t = blockIdx.x * blockDim.x + threadIdx.x;
    int e = t >> 4;
    int q = t & 15;
    if (e >= NE) return;
    int   src = ei[e];
    int   dst = ei[NE + e];
    float nm  = g_norm[e];

    const float4 hv = *(const float4*)(g_h + src * CH + q * 4);
    float mx = nm * hv.x, my = nm * hv.y, mz = nm * hv.z, mw = nm * hv.w;
    float* p = g_act + dst * CH + q * 4;
    asm volatile("red.global.add.v4.f32 [%0], {%1,%2,%3,%4};"
                 :: "l"(p), "f"(mx), "f"(my), "f"(mz), "f"(mw) : "memory");
}

// ---------------- pooling ------------------------------------------------------
__global__ void k_pool_init() {
    int i = blockIdx.x * blockDim.x + threadIdx.x;
    if (i < NG * CH) { g_maxkey[i] = 0x80000000; g_sum[i] = 0.0f; }
    if (i < NG) g_cnt[i] = 0.0f;
}

__global__ void k_pool(const int* __restrict__ batch) {
    int t = blockIdx.x * blockDim.x + threadIdx.x;
    if (t >= NN * CH) return;
    int i = t >> 6, c = t & 63;
    int g = batch[i];
    float v = acc_tanh(g_act[t]);
    atomicMax(&g_maxkey[g * CH + c], fkey(v));
    atomicAdd(&g_sum[g * CH + c], v);
    if (c == 0) atomicAdd(&g_cnt[g], 1.0f);
}

__global__ void k_head(const float* __restrict__ Wout,
                       const float* __restrict__ bout,
                       float* __restrict__ out) {
    int g = blockIdx.x;
    int c = threadIdx.x;  // 64 threads
    float mx   = fdec(g_maxkey[g * CH + c]);
    float mean = g_sum[g * CH + c] / fmaxf(g_cnt[g], 1.0f);
    float v = mx * Wout[c] + mean * Wout[CH + c];
#pragma unroll
    for (int o = 16; o > 0; o >>= 1) v += __shfl_down_sync(0xFFFFFFFF, v, o);
    __shared__ float s[2];
    if ((c & 31) == 0) s[c >> 5] = v;
    __syncthreads();
    if (c == 0) out[g] = s[0] + s[1] + bout[0];
}

// ---------------- launch -------------------------------------------------------
extern "C" void kernel_launch(void* const* d_in, const int* in_sizes, int n_in,
                              void* d_out, int out_size) {
    const float* x     = (const float*)d_in[0];
    const int*   ei    = (const int*)  d_in[1];
    const float* ea    = (const float*)d_in[2];
    const int*   batch = (const int*)  d_in[3];
    const float* W0 = (const float*)d_in[4];  const float* b0 = (const float*)d_in[5];
    const float* W1 = (const float*)d_in[6];  const float* b1 = (const float*)d_in[7];
    const float* W2 = (const float*)d_in[8];  const float* b2 = (const float*)d_in[9];
    const float* W3 = (const float*)d_in[10]; const float* b3 = (const float*)d_in[11];
    const float* Wout = (const float*)d_in[12];
    const float* bout = (const float*)d_in[13];
    float* out = (float*)d_out;

    const int TB = 256;
    const int gemm_blocks    = (NN + 63) / 64;        // 782
    const int scatter_blocks = (NE * 16) / TB;        // 50000

    k_init_deg <<<(NN + TB - 1) / TB, TB>>>();
    k_accum_deg<<<(NE + TB - 1) / TB, TB>>>(ei, ea);
    k_dinv     <<<(NN + TB - 1) / TB, TB>>>();
    k_norm     <<<(NE + TB - 1) / TB, TB>>>(ei, ea);

    // layer 0: 128 -> 64, input x (no tanh)
    k_gemm<INCH, false><<<gemm_blocks, TB>>>(x, W0, b0);
    k_scatter<<<scatter_blocks, TB>>>(ei);
    // layers 1..3: 64 -> 64, input g_act with tanh on read
    k_gemm<CH, true><<<gemm_blocks, TB>>>(nullptr, W1, b1);
    k_scatter<<<scatter_blocks, TB>>>(ei);
    k_gemm<CH, true><<<gemm_blocks, TB>>>(nullptr, W2, b2);
    k_scatter<<<scatter_blocks, TB>>>(ei);
    k_gemm<CH, true><<<gemm_blocks, TB>>>(nullptr, W3, b3);
    k_scatter<<<scatter_blocks, TB>>>(ei);

    k_pool_init<<<(NG * CH + TB - 1) / TB, TB>>>();
    k_pool<<<(NN * CH + TB - 1) / TB, TB>>>(batch);
    k_head<<<NG, 64>>>(Wout, bout, out);
}

// round 2
// speedup vs baseline: 1.2538x; 1.2538x over previous
#include <cuda_runtime.h>
#include <cuda_bf16.h>
#include <cstdint>

#define NN   50000
#define NE   800000
#define NG   64
#define CH   64
#define INCH 128
#define SCAN_B 1024
#define NB   ((NN + SCAN_B - 1) / SCAN_B)   // 49

// ---------------- scratch (static device globals; no allocation) -------------
__device__ float g_dinv[NN];                 // deg (weighted) -> dinv (in place)
__device__ float g_selfc[NN];                // dinv^2 (self-loop norm)
__device__ int   g_deg[NN];                  // in-degree (edges only)
__device__ int   g_rowptr[NN];
__device__ int   g_fill[NN];
__device__ int   g_bsum[64];
__device__ int   g_src_s[NE];                // CSR-sorted src
__device__ float g_norm_s[NE];               // CSR-sorted edge norm
__device__ __align__(16) float g_h[NN * CH];   // h = act @ W
__device__ __align__(16) float g_act[NN * CH]; // layer output (pre-tanh)
__device__ int   g_maxkey[NG * CH];
__device__ float g_sum[NG * CH];
__device__ float g_cnt[NG];

// ---------------- helpers ----------------------------------------------------
__device__ __forceinline__ float acc_tanh(float x) {
    float e = __expf(-2.0f * fabsf(x));
    float t = (1.0f - e) / (1.0f + e);
    return copysignf(t, x);
}
__device__ __forceinline__ int fkey(float f) {
    int i = __float_as_int(f);
    return (i >= 0) ? i : (i ^ 0x7FFFFFFF);
}
__device__ __forceinline__ float fdec(int k) {
    return __int_as_float((k >= 0) ? k : (k ^ 0x7FFFFFFF));
}

// ---------------- preprocessing ----------------------------------------------
__global__ void k_pre_init() {
    int i = blockIdx.x * blockDim.x + threadIdx.x;
    if (i < NN) { g_dinv[i] = 1.0f; g_deg[i] = 0; }
}

__global__ void k_pre_deg(const int* __restrict__ ei, const float* __restrict__ w) {
    int e = blockIdx.x * blockDim.x + threadIdx.x;
    if (e < NE) {
        int dst = ei[NE + e];
        atomicAdd(&g_dinv[dst], w[e]);
        atomicAdd(&g_deg[dst], 1);
    }
}

__global__ void k_pre_dinv() {
    int i = blockIdx.x * blockDim.x + threadIdx.x;
    if (i < NN) {
        float r = rsqrtf(g_dinv[i]);   // weighted deg >= 1 (self-loop)
        g_dinv[i]  = r;
        g_selfc[i] = r * r;
    }
}

// ---------------- CSR build ----------------------------------------------------
__global__ void k_scan_block() {
    __shared__ int s[SCAN_B];
    int tid = threadIdx.x;
    int i   = blockIdx.x * SCAN_B + tid;
    int v   = (i < NN) ? g_deg[i] : 0;
    s[tid] = v; __syncthreads();
#pragma unroll
    for (int o = 1; o < SCAN_B; o <<= 1) {
        int t = (tid >= o) ? s[tid - o] : 0;
        __syncthreads();
        s[tid] += t;
        __syncthreads();
    }
    if (i < NN) g_rowptr[i] = s[tid] - v;        // exclusive, pre-offset
    if (tid == SCAN_B - 1) g_bsum[blockIdx.x] = s[tid];
}

__global__ void k_scan_carry() {
    __shared__ int s[64];
    int tid = threadIdx.x;   // 64 threads
    int v = (tid < NB) ? g_bsum[tid] : 0;
    s[tid] = v; __syncthreads();
#pragma unroll
    for (int o = 1; o < 64; o <<= 1) {
        int t = (tid >= o) ? s[tid - o] : 0;
        __syncthreads();
        s[tid] += t;
        __syncthreads();
    }
    if (tid < NB) g_bsum[tid] = s[tid] - v;      // exclusive block offsets
}

__global__ void k_scan_add() {
    int i = blockIdx.x * blockDim.x + threadIdx.x;
    if (i < NN) {
        int rp = g_rowptr[i] + g_bsum[i >> 10];
        g_rowptr[i] = rp;
        g_fill[i]   = rp;
    }
}

__global__ void k_place(const int* __restrict__ ei, const float* __restrict__ w) {
    int e = blockIdx.x * blockDim.x + threadIdx.x;
    if (e < NE) {
        int src = ei[e];
        int dst = ei[NE + e];
        float nm = g_dinv[src] * w[e] * g_dinv[dst];
        int pos = atomicAdd(&g_fill[dst], 1);
        g_src_s[pos]  = src;
        g_norm_s[pos] = nm;
    }
}

// ---------------- GEMM: h = act @ W --------------------------------------------
// 256 threads, 64 rows/block, K processed in 64-wide chunks.
template <int K, bool FROM_ACT>
__global__ void k_gemm(const float* __restrict__ in,
                       const float* __restrict__ W) {
    __shared__ float sA[64 * 65];
    __shared__ float sW[64 * 64];

    const int tid  = threadIdx.x;
    const int row0 = blockIdx.x * 64;
    const int r    = tid >> 2;
    const int cg   = tid & 3;

    const float* A = FROM_ACT ? g_act : in;

    float4 acc[4];
#pragma unroll
    for (int j = 0; j < 4; ++j) acc[j] = make_float4(0.f, 0.f, 0.f, 0.f);

    for (int kc = 0; kc < K; kc += 64) {
#pragma unroll
        for (int idx = tid; idx < 64 * 64; idx += 256) {
            int rr = idx >> 6, kk = idx & 63;
            int grow = row0 + rr;
            float v = 0.0f;
            if (grow < NN) v = A[grow * K + kc + kk];
            if (FROM_ACT) v = acc_tanh(v);
            sA[rr * 65 + kk] = v;
        }
#pragma unroll
        for (int idx = tid; idx < 64 * 64; idx += 256)
            sW[idx] = W[kc * 64 + idx];
        __syncthreads();

#pragma unroll
        for (int k = 0; k < 64; ++k) {
            float a = sA[r * 65 + k];
            const float4* w4 = (const float4*)(sW + k * 64);
#pragma unroll
            for (int j = 0; j < 4; ++j) {
                float4 w = w4[cg * 4 + j];
                acc[j].x += a * w.x;
                acc[j].y += a * w.y;
                acc[j].z += a * w.z;
                acc[j].w += a * w.w;
            }
        }
        __syncthreads();
    }

    int row = row0 + r;
    if (row < NN) {
        float4* h4 = (float4*)(g_h + row * CH);
#pragma unroll
        for (int j = 0; j < 4; ++j) h4[cg * 4 + j] = acc[j];
    }
}

// ---------------- gather: act[i] = b + selfc[i]*h[i] + sum_e norm*h[src] -------
// one warp per node; lane handles channels [2*lane, 2*lane+1]
__global__ void k_gather(const float* __restrict__ b) {
    int warp = (blockIdx.x * blockDim.x + threadIdx.x) >> 5;
    int lane = threadIdx.x & 31;
    if (warp >= NN) return;
    const int node = warp;
    const int beg  = g_rowptr[node];
    const int deg  = g_deg[node];

    float ax = 0.0f, ay = 0.0f;
    for (int ch = 0; ch < deg; ch += 32) {
        int rem = deg - ch;
        int n = rem < 32 ? rem : 32;
        int s = 0; float nm = 0.0f;
        if (lane < n) {
            int idx = beg + ch + lane;
            s  = g_src_s[idx];
            nm = g_norm_s[idx];
        }
        int j = 0;
        for (; j + 4 <= n; j += 4) {
            int   s0 = __shfl_sync(0xFFFFFFFFu, s,  j);
            float n0 = __shfl_sync(0xFFFFFFFFu, nm, j);
            int   s1 = __shfl_sync(0xFFFFFFFFu, s,  j + 1);
            float n1 = __shfl_sync(0xFFFFFFFFu, nm, j + 1);
            int   s2 = __shfl_sync(0xFFFFFFFFu, s,  j + 2);
            float n2 = __shfl_sync(0xFFFFFFFFu, nm, j + 2);
            int   s3 = __shfl_sync(0xFFFFFFFFu, s,  j + 3);
            float n3 = __shfl_sync(0xFFFFFFFFu, nm, j + 3);
            float2 h0 = *(const float2*)(g_h + s0 * CH + lane * 2);
            float2 h1 = *(const float2*)(g_h + s1 * CH + lane * 2);
            float2 h2 = *(const float2*)(g_h + s2 * CH + lane * 2);
            float2 h3 = *(const float2*)(g_h + s3 * CH + lane * 2);
            ax += n0 * h0.x; ay += n0 * h0.y;
            ax += n1 * h1.x; ay += n1 * h1.y;
            ax += n2 * h2.x; ay += n2 * h2.y;
            ax += n3 * h3.x; ay += n3 * h3.y;
        }
        for (; j < n; ++j) {
            int   bs = __shfl_sync(0xFFFFFFFFu, s,  j);
            float bn = __shfl_sync(0xFFFFFFFFu, nm, j);
            float2 hv = *(const float2*)(g_h + bs * CH + lane * 2);
            ax += bn * hv.x; ay += bn * hv.y;
        }
    }

    float sc = g_selfc[node];
    float2 hs = *(const float2*)(g_h + node * CH + lane * 2);
    float2 bb = *(const float2*)(b + lane * 2);
    float2 o;
    o.x = bb.x + sc * hs.x + ax;
    o.y = bb.y + sc * hs.y + ay;
    *(float2*)(g_act + node * CH + lane * 2) = o;
}

// ---------------- pooling ------------------------------------------------------
__global__ void k_pool_init() {
    int i = blockIdx.x * blockDim.x + threadIdx.x;
    if (i < NG * CH) { g_maxkey[i] = fkey(-3.4e38f); g_sum[i] = 0.0f; }
    if (i < NG) g_cnt[i] = 0.0f;
}

__device__ __forceinline__ void pool_flush(int g, int c, float mx, float sm, int cnt, int rs) {
    if (g < 0) return;
    atomicMax(&g_maxkey[g * CH + c], fkey(mx));
    atomicAdd(&g_sum[g * CH + c], sm);
    if (c == 0) atomicAdd(&g_cnt[g], (float)cnt);
}

// batch_index is sorted: accumulate runs per channel, flush only on graph change.
__global__ void k_pool(const int* __restrict__ batch) {
    int c  = threadIdx.x & 63;
    int rs = threadIdx.x >> 6;           // 0..3
    int base = blockIdx.x * 64;

    int curg = -1; float mx = -3.4e38f, sm = 0.0f; int cnt = 0;
    for (int r = rs; r < 64; r += 4) {
        int node = base + r;
        if (node >= NN) break;
        int g = batch[node];
        float v = acc_tanh(g_act[node * CH + c]);
        if (g != curg) {
            pool_flush(curg, c, mx, sm, cnt, rs);
            curg = g; mx = v; sm = v; cnt = 1;
        } else {
            mx = fmaxf(mx, v); sm += v; cnt++;
        }
    }
    pool_flush(curg, c, mx, sm, cnt, rs);
}

__global__ void k_head(const float* __restrict__ Wout,
                       const float* __restrict__ bout,
                       float* __restrict__ out) {
    int g = blockIdx.x;
    int c = threadIdx.x;  // 64 threads
    float mx   = fdec(g_maxkey[g * CH + c]);
    float mean = g_sum[g * CH + c] / fmaxf(g_cnt[g], 1.0f);
    float v = mx * Wout[c] + mean * Wout[CH + c];
#pragma unroll
    for (int o = 16; o > 0; o >>= 1) v += __shfl_down_sync(0xFFFFFFFF, v, o);
    __shared__ float s[2];
    if ((c & 31) == 0) s[c >> 5] = v;
    __syncthreads();
    if (c == 0) out[g] = s[0] + s[1] + bout[0];
}

// ---------------- launch -------------------------------------------------------
extern "C" void kernel_launch(void* const* d_in, const int* in_sizes, int n_in,
                              void* d_out, int out_size) {
    const float* x     = (const float*)d_in[0];
    const int*   ei    = (const int*)  d_in[1];
    const float* ea    = (const float*)d_in[2];
    const int*   batch = (const int*)  d_in[3];
    const float* W0 = (const float*)d_in[4];  const float* b0 = (const float*)d_in[5];
    const float* W1 = (const float*)d_in[6];  const float* b1 = (const float*)d_in[7];
    const float* W2 = (const float*)d_in[8];  const float* b2 = (const float*)d_in[9];
    const float* W3 = (const float*)d_in[10]; const float* b3 = (const float*)d_in[11];
    const float* Wout = (const float*)d_in[12];
    const float* bout = (const float*)d_in[13];
    float* out = (float*)d_out;

    const int TB = 256;
    const int gemm_blocks   = (NN + 63) / 64;                 // 782
    const int gather_blocks = (NN * 32 + TB - 1) / TB;        // 6250

    // preprocessing + CSR build (once; reused by all 4 layers)
    k_pre_init<<<(NN + TB - 1) / TB, TB>>>();
    k_pre_deg <<<(NE + TB - 1) / TB, TB>>>(ei, ea);
    k_pre_dinv<<<(NN + TB - 1) / TB, TB>>>();
    k_scan_block<<<NB, SCAN_B>>>();
    k_scan_carry<<<1, 64>>>();
    k_scan_add<<<(NN + TB - 1) / TB, TB>>>();
    k_place<<<(NE + TB - 1) / TB, TB>>>(ei, ea);

    // layer 0: 128 -> 64 from x (no tanh)
    k_gemm<INCH, false><<<gemm_blocks, TB>>>(x, W0);
    k_gather<<<gather_blocks, TB>>>(b0);
    // layers 1..3: 64 -> 64 from g_act (tanh on read)
    k_gemm<CH, true><<<gemm_blocks, TB>>>(nullptr, W1);
    k_gather<<<gather_blocks, TB>>>(b1);
    k_gemm<CH, true><<<gemm_blocks, TB>>>(nullptr, W2);
    k_gather<<<gather_blocks, TB>>>(b2);
    k_gemm<CH, true><<<gemm_blocks, TB>>>(nullptr, W3);
    k_gather<<<gather_blocks, TB>>>(b3);

    k_pool_init<<<(NG * CH + TB - 1) / TB, TB>>>();
    k_pool<<<gemm_blocks, TB>>>(batch);
    k_head<<<NG, 64>>>(Wout, bout, out);
}

// round 4
// speedup vs baseline: 2.6402x; 2.1058x over previous
#include <cuda_runtime.h>
#include <cuda_bf16.h>
#include <cstdint>

#define NN   50000
#define NE   800000
#define NG   64
#define CH   64
#define INCH 128
#define SCAN_B 1024
#define NB   ((NN + SCAN_B - 1) / SCAN_B)   // 49

// ---------------- scratch (static device globals; no allocation) -------------
__device__ float g_dinv[NN];                 // weighted deg -> dinv (in place)
__device__ float g_selfc[NN];                // dinv^2 (self-loop norm)
__device__ int   g_deg[NN];                  // in-degree (edges only)
__device__ int   g_rowptr[NN];
__device__ int   g_fill[NN];
__device__ int   g_bsum[64];
__device__ int2  g_edge[NE];                 // CSR-sorted (src, norm-bits)
__device__ __align__(16) float g_h[NN * CH];   // h = act @ W
__device__ __align__(16) float g_act[NN * CH]; // tanh(layer output)
__device__ int   g_maxkey[NG * CH];
__device__ float g_sum[NG * CH];
__device__ float g_cnt[NG];

// ---------------- helpers ----------------------------------------------------
__device__ __forceinline__ float acc_tanh(float x) {
    float e = __expf(-2.0f * fabsf(x));
    float t = __fdividef(1.0f - e, 1.0f + e);
    return copysignf(t, x);
}
__device__ __forceinline__ int fkey(float f) {
    int i = __float_as_int(f);
    return (i >= 0) ? i : (i ^ 0x7FFFFFFF);
}
__device__ __forceinline__ float fdec(int k) {
    return __int_as_float((k >= 0) ? k : (k ^ 0x7FFFFFFF));
}

// ---------------- preprocessing ----------------------------------------------
__global__ void k_pre_init() {
    int i = blockIdx.x * blockDim.x + threadIdx.x;
    if (i < NN) { g_dinv[i] = 1.0f; g_deg[i] = 0; }
}

__global__ void k_pre_deg(const int* __restrict__ ei, const float* __restrict__ w) {
    int e = blockIdx.x * blockDim.x + threadIdx.x;
    if (e < NE) {
        int dst = ei[NE + e];
        atomicAdd(&g_dinv[dst], w[e]);
        atomicAdd(&g_deg[dst], 1);
    }
}

__global__ void k_pre_dinv() {
    int i = blockIdx.x * blockDim.x + threadIdx.x;
    if (i < NN) {
        float r = rsqrtf(g_dinv[i]);   // weighted deg >= 1 (self-loop)
        g_dinv[i]  = r;
        g_selfc[i] = r * r;
    }
}

// ---------------- CSR build ----------------------------------------------------
__global__ void k_scan_block() {
    __shared__ int s[SCAN_B];
    int tid = threadIdx.x;
    int i   = blockIdx.x * SCAN_B + tid;
    int v   = (i < NN) ? g_deg[i] : 0;
    s[tid] = v; __syncthreads();
#pragma unroll
    for (int o = 1; o < SCAN_B; o <<= 1) {
        int t = (tid >= o) ? s[tid - o] : 0;
        __syncthreads();
        s[tid] += t;
        __syncthreads();
    }
    if (i < NN) g_rowptr[i] = s[tid] - v;        // exclusive, pre-offset
    if (tid == SCAN_B - 1) g_bsum[blockIdx.x] = s[tid];
}

__global__ void k_scan_carry() {
    __shared__ int s[64];
    int tid = threadIdx.x;   // 64 threads
    int v = (tid < NB) ? g_bsum[tid] : 0;
    s[tid] = v; __syncthreads();
#pragma unroll
    for (int o = 1; o < 64; o <<= 1) {
        int t = (tid >= o) ? s[tid - o] : 0;
        __syncthreads();
        s[tid] += t;
        __syncthreads();
    }
    if (tid < NB) g_bsum[tid] = s[tid] - v;      // exclusive block offsets
}

__global__ void k_scan_add() {
    int i = blockIdx.x * blockDim.x + threadIdx.x;
    if (i < NN) {
        int rp = g_rowptr[i] + g_bsum[i >> 10];
        g_rowptr[i] = rp;
        g_fill[i]   = rp;
    }
}

__global__ void k_place(const int* __restrict__ ei, const float* __restrict__ w) {
    int e = blockIdx.x * blockDim.x + threadIdx.x;
    if (e < NE) {
        int src = ei[e];
        int dst = ei[NE + e];
        float nm = g_dinv[src] * w[e] * g_dinv[dst];
        int pos = atomicAdd(&g_fill[dst], 1);
        g_edge[pos] = make_int2(src, __float_as_int(nm));
    }
}

// ---------------- GEMM: h = A @ W (A already activated) -------------------------
// 256 threads; block = 64 rows x 64 cols; thread = 4 rows x 4 cols.
// FROM_ACT: read the device-global g_act (resolved IN device code).
template <int K, bool FROM_ACT>
__global__ void k_gemm(const float* __restrict__ in, const float* __restrict__ W) {
    __shared__ float sA[64 * 68];
    __shared__ float sW[64 * 64];

    const int tid  = threadIdx.x;
    const int row0 = blockIdx.x * 64;
    const int rowg = tid >> 4;    // 0..15, 4 rows each
    const int colg = tid & 15;    // 0..15, 4 cols each

    const float* A = FROM_ACT ? (const float*)g_act : in;

    float4 acc[4];
#pragma unroll
    for (int i = 0; i < 4; ++i) acc[i] = make_float4(0.f, 0.f, 0.f, 0.f);

    for (int kc = 0; kc < K; kc += 64) {
        // stage A tile: 64 rows x 64 k, float4 loads
#pragma unroll
        for (int idx = tid; idx < 64 * 16; idx += 256) {
            int rr = idx >> 4, k4 = (idx & 15) * 4;
            int grow = row0 + rr;
            float4 v = make_float4(0.f, 0.f, 0.f, 0.f);
            if (grow < NN) v = *(const float4*)(A + (size_t)grow * K + kc + k4);
            *(float4*)(sA + rr * 68 + k4) = v;
        }
        // stage W chunk
#pragma unroll
        for (int idx = tid; idx < 64 * 16; idx += 256) {
            int rr = idx >> 4, c4 = (idx & 15) * 4;
            *(float4*)(sW + rr * 64 + c4) = *(const float4*)(W + (size_t)(kc + rr) * 64 + c4);
        }
        __syncthreads();

#pragma unroll
        for (int k = 0; k < 64; ++k) {
            float4 w = *(const float4*)(sW + k * 64 + colg * 4);
            float a0 = sA[(rowg * 4 + 0) * 68 + k];
            float a1 = sA[(rowg * 4 + 1) * 68 + k];
            float a2 = sA[(rowg * 4 + 2) * 68 + k];
            float a3 = sA[(rowg * 4 + 3) * 68 + k];
            acc[0].x += a0 * w.x; acc[0].y += a0 * w.y; acc[0].z += a0 * w.z; acc[0].w += a0 * w.w;
            acc[1].x += a1 * w.x; acc[1].y += a1 * w.y; acc[1].z += a1 * w.z; acc[1].w += a1 * w.w;
            acc[2].x += a2 * w.x; acc[2].y += a2 * w.y; acc[2].z += a2 * w.z; acc[2].w += a2 * w.w;
            acc[3].x += a3 * w.x; acc[3].y += a3 * w.y; acc[3].z += a3 * w.z; acc[3].w += a3 * w.w;
        }
        __syncthreads();
    }

    int row = row0 + rowg * 4;
#pragma unroll
    for (int i = 0; i < 4; ++i)
        if (row + i < NN) *(float4*)(g_h + (size_t)(row + i) * CH + colg * 4) = acc[i];
}

// ------- gather: act[i] = tanh(b + selfc[i]*h[i] + sum_e norm*h[src]) ----------
// one warp per node; 2 edges per iteration; lane = (half, c4): float4 channels.
__global__ void k_gather(const float* __restrict__ b) {
    int warp = (blockIdx.x * blockDim.x + threadIdx.x) >> 5;
    int lane = threadIdx.x & 31;
    if (warp >= NN) return;
    const int node = warp;
    const int beg  = g_rowptr[node];
    const int deg  = g_deg[node];
    const int half = lane >> 4;
    const int c4   = (lane & 15) * 4;

    float ax = 0.f, ay = 0.f, az = 0.f, aw = 0.f;
    for (int ch = 0; ch < deg; ch += 32) {
        int rem = deg - ch;
        int n = rem < 32 ? rem : 32;
        int s = node; float nm = 0.0f;     // inactive lanes: nm=0 contributes nothing
        if (lane < n) {
            int2 e = g_edge[beg + ch + lane];
            s = e.x; nm = __int_as_float(e.y);
        }
        int npairs = (n + 1) >> 1;
#pragma unroll 4
        for (int j = 0; j < npairs; ++j) {
            int   se = __shfl_sync(0xFFFFFFFFu, s,  2 * j + half);
            float ne = __shfl_sync(0xFFFFFFFFu, nm, 2 * j + half);
            float4 hv = *(const float4*)(g_h + (size_t)se * CH + c4);
            ax += ne * hv.x; ay += ne * hv.y; az += ne * hv.z; aw += ne * hv.w;
        }
    }
    // combine the two edge-parity halves
    ax += __shfl_xor_sync(0xFFFFFFFFu, ax, 16);
    ay += __shfl_xor_sync(0xFFFFFFFFu, ay, 16);
    az += __shfl_xor_sync(0xFFFFFFFFu, az, 16);
    aw += __shfl_xor_sync(0xFFFFFFFFu, aw, 16);

    if (half == 0) {
        float sc = g_selfc[node];
        float4 hs = *(const float4*)(g_h + (size_t)node * CH + c4);
        float4 bb = *(const float4*)(b + c4);
        float4 o;
        o.x = acc_tanh(bb.x + sc * hs.x + ax);
        o.y = acc_tanh(bb.y + sc * hs.y + ay);
        o.z = acc_tanh(bb.z + sc * hs.z + az);
        o.w = acc_tanh(bb.w + sc * hs.w + aw);
        *(float4*)(g_act + (size_t)node * CH + c4) = o;
    }
}

// ---------------- pooling (g_act already tanh'd) --------------------------------
__global__ void k_pool_init() {
    int i = blockIdx.x * blockDim.x + threadIdx.x;
    if (i < NG * CH) { g_maxkey[i] = fkey(-3.4e38f); g_sum[i] = 0.0f; }
    if (i < NG) g_cnt[i] = 0.0f;
}

__device__ __forceinline__ void pool_flush(int g, int c, float mx, float sm, int cnt) {
    if (g < 0) return;
    atomicMax(&g_maxkey[g * CH + c], fkey(mx));
    atomicAdd(&g_sum[g * CH + c], sm);
    if (c == 0) atomicAdd(&g_cnt[g], (float)cnt);
}

// batch_index is sorted: accumulate runs per channel, flush only on graph change.
__global__ void k_pool(const int* __restrict__ batch) {
    int c  = threadIdx.x & 63;
    int rs = threadIdx.x >> 6;           // 0..3
    int base = blockIdx.x * 64;

    int curg = -1; float mx = -3.4e38f, sm = 0.0f; int cnt = 0;
    for (int r = rs; r < 64; r += 4) {
        int node = base + r;
        if (node >= NN) break;
        int g = batch[node];
        float v = g_act[(size_t)node * CH + c];
        if (g != curg) {
            pool_flush(curg, c, mx, sm, cnt);
            curg = g; mx = v; sm = v; cnt = 1;
        } else {
            mx = fmaxf(mx, v); sm += v; cnt++;
        }
    }
    pool_flush(curg, c, mx, sm, cnt);
}

__global__ void k_head(const float* __restrict__ Wout,
                       const float* __restrict__ bout,
                       float* __restrict__ out) {
    int g = blockIdx.x;
    int c = threadIdx.x;  // 64 threads
    float mx   = fdec(g_maxkey[g * CH + c]);
    float mean = g_sum[g * CH + c] / fmaxf(g_cnt[g], 1.0f);
    float v = mx * Wout[c] + mean * Wout[CH + c];
#pragma unroll
    for (int o = 16; o > 0; o >>= 1) v += __shfl_down_sync(0xFFFFFFFF, v, o);
    __shared__ float s[2];
    if ((c & 31) == 0) s[c >> 5] = v;
    __syncthreads();
    if (c == 0) out[g] = s[0] + s[1] + bout[0];
}

// ---------------- launch -------------------------------------------------------
extern "C" void kernel_launch(void* const* d_in, const int* in_sizes, int n_in,
                              void* d_out, int out_size) {
    const float* x     = (const float*)d_in[0];
    const int*   ei    = (const int*)  d_in[1];
    const float* ea    = (const float*)d_in[2];
    const int*   batch = (const int*)  d_in[3];
    const float* W0 = (const float*)d_in[4];  const float* b0 = (const float*)d_in[5];
    const float* W1 = (const float*)d_in[6];  const float* b1 = (const float*)d_in[7];
    const float* W2 = (const float*)d_in[8];  const float* b2 = (const float*)d_in[9];
    const float* W3 = (const float*)d_in[10]; const float* b3 = (const float*)d_in[11];
    const float* Wout = (const float*)d_in[12];
    const float* bout = (const float*)d_in[13];
    float* out = (float*)d_out;

    const int TB = 256;
    const int gemm_blocks   = (NN + 63) / 64;                 // 782
    const int gather_blocks = (NN * 32 + TB - 1) / TB;        // 6250

    // preprocessing + CSR build (once; reused by all 4 layers)
    k_pre_init<<<(NN + TB - 1) / TB, TB>>>();
    k_pre_deg <<<(NE + TB - 1) / TB, TB>>>(ei, ea);
    k_pre_dinv<<<(NN + TB - 1) / TB, TB>>>();
    k_scan_block<<<NB, SCAN_B>>>();
    k_scan_carry<<<1, 64>>>();
    k_scan_add<<<(NN + TB - 1) / TB, TB>>>();
    k_place<<<(NE + TB - 1) / TB, TB>>>(ei, ea);

    // layer 0: 128 -> 64 from x
    k_gemm<INCH, false><<<gemm_blocks, TB>>>(x, W0);
    k_gather<<<gather_blocks, TB>>>(b0);
    // layers 1..3: 64 -> 64 from g_act (already tanh'd), resolved in device code
    k_gemm<CH, true><<<gemm_blocks, TB>>>(nullptr, W1);
    k_gather<<<gather_blocks, TB>>>(b1);
    k_gemm<CH, true><<<gemm_blocks, TB>>>(nullptr, W2);
    k_gather<<<gather_blocks, TB>>>(b2);
    k_gemm<CH, true><<<gemm_blocks, TB>>>(nullptr, W3);
    k_gather<<<gather_blocks, TB>>>(b3);

    k_pool_init<<<(NG * CH + TB - 1) / TB, TB>>>();
    k_pool<<<gemm_blocks, TB>>>(batch);
    k_head<<<NG, 64>>>(Wout, bout, out);
}